// round 14
// baseline (speedup 1.0000x reference)
#include <cuda_runtime.h>
#include <cstdint>
#include <cstddef>

// Ridge_51178830299316 — dual formulation, round 14.
// K1: Gram with NO smem (direct __ldg through L1; removes the 4-way LDS bank
//     conflicts that made the smem version conflict-bound).
// K2: fused Cholesky+forward-sub with tile-structured strip-first lookahead:
//     per panel: strip (4x4 register tiles, all 512 threads) -> barrier ->
//     {solver warps 0-5: A(k+1); bar1; B(k+1)->LT[cur^1]} || {warps 6-15:
//     C2(k) on LT[cur]}. Phase A uses a double-buffered colbuf (one syncwarp
//     per column instead of two).

#define NPTS   256
#define DIM    128
#define BATCH  32
#define K2T    512
#define APACK_SIZE 33280

__host__ __device__ __forceinline__ int rowbase(int r) {
    const int q = r >> 2, rem = r & 3;
    return 8 * q * (q - 1) + 4 * rem * q + 4 * r;
}

__device__ float g_gram[BATCH][APACK_SIZE];

// ============================ K1: Gram (smem-free) ========================
__global__ void __launch_bounds__(256) gram_kernel(const float* __restrict__ data)
{
    const int bid = blockIdx.x;
    const int b = bid / 36, t36 = bid % 36;
    int ti = 0;
    while ((ti + 1) * (ti + 2) / 2 <= t36) ++ti;
    const int tj = t36 - ti * (ti + 1) / 2;

    const float* Xb = data + (size_t)b * NPTS * DIM;
    const int tid = threadIdx.x;
    const int ty = tid >> 4, tx = tid & 15;
    const int gr0 = ti * 32 + 2 * ty;
    const int gc0 = tj * 32 + 2 * tx;

    const float4* xi0p = reinterpret_cast<const float4*>(Xb + (size_t)gr0 * DIM);
    const float4* xi1p = reinterpret_cast<const float4*>(Xb + (size_t)(gr0 + 1) * DIM);
    const float4* xj0p = reinterpret_cast<const float4*>(Xb + (size_t)gc0 * DIM);
    const float4* xj1p = reinterpret_cast<const float4*>(Xb + (size_t)(gc0 + 1) * DIM);

    float a00 = 0.f, a01 = 0.f, a10 = 0.f, a11 = 0.f;
    #pragma unroll 8
    for (int k4 = 0; k4 < 32; ++k4) {
        const float4 xi0 = __ldg(xi0p + k4);
        const float4 xi1 = __ldg(xi1p + k4);
        const float4 xj0 = __ldg(xj0p + k4);
        const float4 xj1 = __ldg(xj1p + k4);
        a00 += xi0.x*xj0.x + xi0.y*xj0.y + xi0.z*xj0.z + xi0.w*xj0.w;
        a01 += xi0.x*xj1.x + xi0.y*xj1.y + xi0.z*xj1.z + xi0.w*xj1.w;
        a10 += xi1.x*xj0.x + xi1.y*xj0.y + xi1.z*xj0.z + xi1.w*xj0.w;
        a11 += xi1.x*xj1.x + xi1.y*xj1.y + xi1.z*xj1.z + xi1.w*xj1.w;
    }
    float* gg = g_gram[b];
    if (gr0 >= gc0)         gg[rowbase(gr0)     + gc0]     = a00 + (gr0     == gc0     ? 1.f : 0.f);
    if (gr0 >= gc0 + 1)     gg[rowbase(gr0)     + gc0 + 1] = a01 + (gr0     == gc0 + 1 ? 1.f : 0.f);
    if (gr0 + 1 >= gc0)     gg[rowbase(gr0 + 1) + gc0]     = a10 + (gr0 + 1 == gc0     ? 1.f : 0.f);
    if (gr0 + 1 >= gc0 + 1) gg[rowbase(gr0 + 1) + gc0 + 1] = a11 + (gr0 + 1 == gc0 + 1 ? 1.f : 0.f);
}

// ==================== K2: pipelined Cholesky + forward sub ================
struct K2Smem {
    float A[APACK_SIZE];
    float u[NPTS];
    float z[32];
    float invD[32];
    float D[32][32];
    float LT[2][32][NPTS];
    float colbuf[2][32];
};

__device__ __forceinline__ void phaseA(K2Smem& sm, int kp, int tid)
{
    const int P = 32 * kp;
    const int rp = tid, gr = P + rp, rb = rowbase(gr);
    float arow[32];
    #pragma unroll
    for (int c = 0; c < 32; ++c) arow[c] = sm.A[rb + P + c];  // c>rp garbage, unused
    float ur = sm.u[gr];
    #pragma unroll
    for (int c = 0; c < 32; ++c) {
        const float d  = __shfl_sync(0xffffffffu, arow[c], c);
        const float uc = __shfl_sync(0xffffffffu, ur, c);
        const float rs = rsqrtf(d);
        const float zc = uc * rs;
        const float lrc = (rp > c) ? arow[c] * rs : 0.f;
        if (rp == c) { arow[c] = d * rs; sm.z[c] = zc; sm.invD[c] = rs; }
        if (rp > c)  { arow[c] = lrc; ur -= lrc * zc; }
        sm.colbuf[c & 1][rp] = lrc;
        __syncwarp();
        float cb[32];
        #pragma unroll
        for (int q = 0; q < 8; ++q)
            *reinterpret_cast<float4*>(&cb[4 * q]) =
                *reinterpret_cast<const float4*>(&sm.colbuf[c & 1][4 * q]);
        #pragma unroll
        for (int j = 0; j < 32; ++j)
            if (j > c) arow[j] -= lrc * cb[j];
        // no trailing syncwarp: next column writes the other colbuf
    }
    sm.u[gr] = ur;
    #pragma unroll
    for (int q = 0; q < 8; ++q)
        *reinterpret_cast<float4*>(&sm.D[rp][4 * q]) =
            *reinterpret_cast<const float4*>(&arow[4 * q]);
}

__device__ __forceinline__ void phaseB(K2Smem& sm, int kp, int buf, int tid)
{
    const int P = 32 * kp;
    const int R = NPTS - P - 32;
    if (tid < R) {
        const int gr = P + 32 + tid, rb = rowbase(gr);
        float Lr[32];
        #pragma unroll
        for (int c = 0; c < 32; ++c) {
            float acc = sm.A[rb + P + c];
            #pragma unroll
            for (int p = 0; p < 32; ++p)
                if (p < c) acc -= Lr[p] * sm.D[c][p];
            Lr[c] = acc * sm.invD[c];
        }
        float du = 0.f;
        #pragma unroll
        for (int c = 0; c < 32; ++c) du += Lr[c] * sm.z[c];
        sm.u[gr] -= du;
        #pragma unroll
        for (int c = 0; c < 32; ++c) sm.LT[buf][c][gr] = Lr[c];
    }
}

// strip: cols [Pn, Pn+32), rows [Pn, 256), 4x4 register tiles, all threads.
__device__ __forceinline__ void strip_update(K2Smem& sm, int Pn, int cur, int tid)
{
    const int nrow4 = (NPTS - Pn) >> 2;
    const int tr4 = tid >> 3, tc4 = tid & 7;
    if (tr4 >= nrow4 || tc4 > tr4) return;     // above diagonal / out of range
    const int r0 = Pn + 4 * tr4, c0 = Pn + 4 * tc4;

    int rb[4];
    float acc[4][4];
    #pragma unroll
    for (int i = 0; i < 4; ++i) {
        rb[i] = rowbase(r0 + i);
        const float4 v = *reinterpret_cast<const float4*>(&sm.A[rb[i] + c0]);
        acc[i][0] = v.x; acc[i][1] = v.y; acc[i][2] = v.z; acc[i][3] = v.w;
    }
    #pragma unroll 8
    for (int p = 0; p < 32; ++p) {
        const float4 lr = *reinterpret_cast<const float4*>(&sm.LT[cur][p][r0]);
        const float4 lc = *reinterpret_cast<const float4*>(&sm.LT[cur][p][c0]);
        const float lrv[4] = {lr.x, lr.y, lr.z, lr.w};
        const float lcv[4] = {lc.x, lc.y, lc.z, lc.w};
        #pragma unroll
        for (int i = 0; i < 4; ++i)
            #pragma unroll
            for (int j = 0; j < 4; ++j)
                acc[i][j] -= lrv[i] * lcv[j];
    }
    if (tc4 < tr4) {
        #pragma unroll
        for (int i = 0; i < 4; ++i)
            *reinterpret_cast<float4*>(&sm.A[rb[i] + c0]) =
                make_float4(acc[i][0], acc[i][1], acc[i][2], acc[i][3]);
    } else {   // diagonal tile: store c <= r only
        #pragma unroll
        for (int i = 0; i < 4; ++i)
            #pragma unroll
            for (int j = 0; j < 4; ++j)
                if (j <= i) sm.A[rb[i] + c0 + j] = acc[i][j];
    }
}

// C2: trailing update excluding the strip (tc >= 4(k+2)), 320 threads.
__device__ __forceinline__ void phaseC2(K2Smem& sm, int k, int cur, int a0)
{
    const int c0t = 4 * (k + 2);
    const int mrem = 32 - c0t;
    if (mrem <= 0) return;
    const int Tact = mrem * (mrem + 1) / 2;
    for (int a = a0; a < Tact; a += 320) {
        int t = (int)(0.5f * (__fsqrt_rn(8.f * a + 1.f) - 1.f));
        while ((t + 1) * (t + 2) / 2 <= a) ++t;
        while (t * (t + 1) / 2 > a) --t;
        const int tc = 31 - t;
        const int tr = 31 - (a - t * (t + 1) / 2);
        const int r0 = 8 * tr, cc0 = 8 * tc;

        float acc[8][8];
        int rbs[8];
        #pragma unroll
        for (int i = 0; i < 8; ++i) {
            rbs[i] = rowbase(r0 + i);
            const float4 v0 = *reinterpret_cast<const float4*>(&sm.A[rbs[i] + cc0]);
            const float4 v1 = *reinterpret_cast<const float4*>(&sm.A[rbs[i] + cc0 + 4]);
            acc[i][0] = v0.x; acc[i][1] = v0.y; acc[i][2] = v0.z; acc[i][3] = v0.w;
            acc[i][4] = v1.x; acc[i][5] = v1.y; acc[i][6] = v1.z; acc[i][7] = v1.w;
        }
        #pragma unroll 4
        for (int p = 0; p < 32; ++p) {
            const float4 lr0 = *reinterpret_cast<const float4*>(&sm.LT[cur][p][r0]);
            const float4 lr1 = *reinterpret_cast<const float4*>(&sm.LT[cur][p][r0 + 4]);
            const float4 lc0 = *reinterpret_cast<const float4*>(&sm.LT[cur][p][cc0]);
            const float4 lc1 = *reinterpret_cast<const float4*>(&sm.LT[cur][p][cc0 + 4]);
            const float lr[8] = {lr0.x, lr0.y, lr0.z, lr0.w, lr1.x, lr1.y, lr1.z, lr1.w};
            const float lc[8] = {lc0.x, lc0.y, lc0.z, lc0.w, lc1.x, lc1.y, lc1.z, lc1.w};
            #pragma unroll
            for (int i = 0; i < 8; ++i)
                #pragma unroll
                for (int j = 0; j < 8; ++j)
                    acc[i][j] -= lr[i] * lc[j];
        }
        if (tr != tc) {
            #pragma unroll
            for (int i = 0; i < 8; ++i) {
                *reinterpret_cast<float4*>(&sm.A[rbs[i] + cc0]) =
                    make_float4(acc[i][0], acc[i][1], acc[i][2], acc[i][3]);
                *reinterpret_cast<float4*>(&sm.A[rbs[i] + cc0 + 4]) =
                    make_float4(acc[i][4], acc[i][5], acc[i][6], acc[i][7]);
            }
        } else {
            #pragma unroll
            for (int i = 0; i < 8; ++i)
                #pragma unroll
                for (int j = 0; j < 8; ++j)
                    if (j <= i) sm.A[rbs[i] + cc0 + j] = acc[i][j];
        }
    }
}

__global__ void __launch_bounds__(K2T, 1)
chol_kernel(const float* __restrict__ targets, float* __restrict__ out)
{
    extern __shared__ char smraw[];
    K2Smem& sm = *reinterpret_cast<K2Smem*>(smraw);
    const int b = blockIdx.x, tid = threadIdx.x;

    {
        const float4* src = reinterpret_cast<const float4*>(g_gram[b]);
        float4* dst = reinterpret_cast<float4*>(sm.A);
        for (int i = tid; i < APACK_SIZE / 4; i += K2T) dst[i] = src[i];
    }
    if (tid < NPTS) sm.u[tid] = targets[(size_t)b * NPTS + tid];
    __syncthreads();

    // ---- Prologue: A(0), B(0) -> LT[0] ----
    if (tid < 32) phaseA(sm, 0, tid);
    __syncthreads();
    phaseB(sm, 0, 0, tid);       // internal guard tid < 224
    __syncthreads();

    int cur = 0;
    #pragma unroll 1
    for (int k = 0; k < 7; ++k) {
        const int Pn = 32 * (k + 1);

        strip_update(sm, Pn, cur, tid);
        __syncthreads();

        if (tid < 192) {
            if (tid < 32) phaseA(sm, k + 1, tid);
            asm volatile("bar.sync 1, 192;" ::: "memory");
            phaseB(sm, k + 1, cur ^ 1, tid);     // internal guard
        } else {
            phaseC2(sm, k, cur, tid - 192);
        }
        __syncthreads();
        cur ^= 1;
    }

    for (int j = tid; j < NPTS; j += K2T)
        out[(size_t)b * NPTS + j] = targets[(size_t)b * NPTS + j] - sm.u[j];
}

extern "C" void kernel_launch(void* const* d_in, const int* in_sizes, int n_in,
                              void* d_out, int out_size)
{
    const float* data    = (const float*)d_in[0];   // [32, 256, 128] f32
    const float* targets = (const float*)d_in[1];   // [32, 256]      f32
    float* out = (float*)d_out;                     // [32, 256]      f32

    gram_kernel<<<BATCH * 36, 256>>>(data);

    const size_t smem_bytes = sizeof(K2Smem);
    cudaFuncSetAttribute(chol_kernel,
                         cudaFuncAttributeMaxDynamicSharedMemorySize,
                         (int)smem_bytes);
    chol_kernel<<<BATCH, K2T, smem_bytes>>>(targets, out);
}

// round 15
// speedup vs baseline: 1.6870x; 1.6870x over previous
#include <cuda_runtime.h>
#include <cstdint>
#include <cstddef>

// Ridge_51178830299316 — dual formulation, round 15.
// K2: byte-identical to round 14 (measured 66.8us: strip-first lookahead,
//     A/B solver warps overlapped with C2 update warps, dbl-buffered LT).
// K1: back to smem, but CONFLICT-FREE: the Xj operand is stored transposed
//     (k-major, XjT[128][36]); lane tx reads XjT[k][2tx] as float2 -> banks
//     (36k+2tx) mod 32 tile all 32 banks exactly once. Xi stays row-major
//     (broadcast float4). This removes the 4-way LDS conflicts of the R12
//     version and the LDG gather catastrophe of the R14 version.

#define NPTS   256
#define DIM    128
#define BATCH  32
#define K2T    512
#define APACK_SIZE 33280

__host__ __device__ __forceinline__ int rowbase(int r) {
    const int q = r >> 2, rem = r & 3;
    return 8 * q * (q - 1) + 4 * rem * q + 4 * r;
}

__device__ float g_gram[BATCH][APACK_SIZE];

// ============================ K1: Gram (conflict-free smem) ===============
__global__ void __launch_bounds__(256) gram_kernel(const float* __restrict__ data)
{
    const int bid = blockIdx.x;
    const int b = bid / 36, t36 = bid % 36;
    int ti = 0;
    while ((ti + 1) * (ti + 2) / 2 <= t36) ++ti;
    const int tj = t36 - ti * (ti + 1) / 2;

    __shared__ float Xi[32][132];     // row-major: rows of the ti panel
    __shared__ float XjT[128][36];    // k-major (transposed): tj panel

    const float* Xb = data + (size_t)b * NPTS * DIM;
    const int tid = threadIdx.x;

    // Xi load: warp w handles row w (per 256-thread pass: rows q>>5),
    // lanes cover the 32 float4 columns -> coalesced LDG + conflict-free STS.
    for (int q = tid; q < 1024; q += 256) {
        const int r = q >> 5, c4 = q & 31;
        *reinterpret_cast<float4*>(&Xi[r][c4 * 4]) =
            reinterpret_cast<const float4*>(Xb + (size_t)(ti * 32 + r) * DIM)[c4];
    }
    // XjT load: lane j = row, c4 fixed per warp-pass. Global is strided
    // (row-major X), but panels are L2-resident across ~9 CTAs. STS scatter:
    // XjT[4c4+e][j] with lanes varying j -> consecutive banks, conflict-free.
    for (int q = tid; q < 1024; q += 256) {
        const int j = q & 31, c4 = q >> 5;
        const float4 v =
            reinterpret_cast<const float4*>(Xb + (size_t)(tj * 32 + j) * DIM)[c4];
        XjT[4 * c4 + 0][j] = v.x;
        XjT[4 * c4 + 1][j] = v.y;
        XjT[4 * c4 + 2][j] = v.z;
        XjT[4 * c4 + 3][j] = v.w;
    }
    __syncthreads();

    const int ty = tid >> 4, tx = tid & 15;
    const int r0 = 2 * ty, c0 = 2 * tx;
    float a00 = 0.f, a01 = 0.f, a10 = 0.f, a11 = 0.f;
    #pragma unroll 4
    for (int k4 = 0; k4 < 32; ++k4) {
        const float4 xi0 = *reinterpret_cast<const float4*>(&Xi[r0][k4 * 4]);
        const float4 xi1 = *reinterpret_cast<const float4*>(&Xi[r0 + 1][k4 * 4]);
        const float xi0v[4] = {xi0.x, xi0.y, xi0.z, xi0.w};
        const float xi1v[4] = {xi1.x, xi1.y, xi1.z, xi1.w};
        #pragma unroll
        for (int e = 0; e < 4; ++e) {
            const float2 xj =
                *reinterpret_cast<const float2*>(&XjT[k4 * 4 + e][c0]);
            a00 = fmaf(xi0v[e], xj.x, a00);
            a01 = fmaf(xi0v[e], xj.y, a01);
            a10 = fmaf(xi1v[e], xj.x, a10);
            a11 = fmaf(xi1v[e], xj.y, a11);
        }
    }
    const int gr0 = ti * 32 + r0, gc0 = tj * 32 + c0;
    float* gg = g_gram[b];
    if (gr0 >= gc0)         gg[rowbase(gr0)     + gc0]     = a00 + (gr0     == gc0     ? 1.f : 0.f);
    if (gr0 >= gc0 + 1)     gg[rowbase(gr0)     + gc0 + 1] = a01 + (gr0     == gc0 + 1 ? 1.f : 0.f);
    if (gr0 + 1 >= gc0)     gg[rowbase(gr0 + 1) + gc0]     = a10 + (gr0 + 1 == gc0     ? 1.f : 0.f);
    if (gr0 + 1 >= gc0 + 1) gg[rowbase(gr0 + 1) + gc0 + 1] = a11 + (gr0 + 1 == gc0 + 1 ? 1.f : 0.f);
}

// ==================== K2: pipelined Cholesky + forward sub (R14) ==========
struct K2Smem {
    float A[APACK_SIZE];
    float u[NPTS];
    float z[32];
    float invD[32];
    float D[32][32];
    float LT[2][32][NPTS];
    float colbuf[2][32];
};

__device__ __forceinline__ void phaseA(K2Smem& sm, int kp, int tid)
{
    const int P = 32 * kp;
    const int rp = tid, gr = P + rp, rb = rowbase(gr);
    float arow[32];
    #pragma unroll
    for (int c = 0; c < 32; ++c) arow[c] = sm.A[rb + P + c];  // c>rp garbage, unused
    float ur = sm.u[gr];
    #pragma unroll
    for (int c = 0; c < 32; ++c) {
        const float d  = __shfl_sync(0xffffffffu, arow[c], c);
        const float uc = __shfl_sync(0xffffffffu, ur, c);
        const float rs = rsqrtf(d);
        const float zc = uc * rs;
        const float lrc = (rp > c) ? arow[c] * rs : 0.f;
        if (rp == c) { arow[c] = d * rs; sm.z[c] = zc; sm.invD[c] = rs; }
        if (rp > c)  { arow[c] = lrc; ur -= lrc * zc; }
        sm.colbuf[c & 1][rp] = lrc;
        __syncwarp();
        float cb[32];
        #pragma unroll
        for (int q = 0; q < 8; ++q)
            *reinterpret_cast<float4*>(&cb[4 * q]) =
                *reinterpret_cast<const float4*>(&sm.colbuf[c & 1][4 * q]);
        #pragma unroll
        for (int j = 0; j < 32; ++j)
            if (j > c) arow[j] -= lrc * cb[j];
    }
    sm.u[gr] = ur;
    #pragma unroll
    for (int q = 0; q < 8; ++q)
        *reinterpret_cast<float4*>(&sm.D[rp][4 * q]) =
            *reinterpret_cast<const float4*>(&arow[4 * q]);
}

__device__ __forceinline__ void phaseB(K2Smem& sm, int kp, int buf, int tid)
{
    const int P = 32 * kp;
    const int R = NPTS - P - 32;
    if (tid < R) {
        const int gr = P + 32 + tid, rb = rowbase(gr);
        float Lr[32];
        #pragma unroll
        for (int c = 0; c < 32; ++c) {
            float acc = sm.A[rb + P + c];
            #pragma unroll
            for (int p = 0; p < 32; ++p)
                if (p < c) acc -= Lr[p] * sm.D[c][p];
            Lr[c] = acc * sm.invD[c];
        }
        float du = 0.f;
        #pragma unroll
        for (int c = 0; c < 32; ++c) du += Lr[c] * sm.z[c];
        sm.u[gr] -= du;
        #pragma unroll
        for (int c = 0; c < 32; ++c) sm.LT[buf][c][gr] = Lr[c];
    }
}

__device__ __forceinline__ void strip_update(K2Smem& sm, int Pn, int cur, int tid)
{
    const int nrow4 = (NPTS - Pn) >> 2;
    const int tr4 = tid >> 3, tc4 = tid & 7;
    if (tr4 >= nrow4 || tc4 > tr4) return;
    const int r0 = Pn + 4 * tr4, c0 = Pn + 4 * tc4;

    int rb[4];
    float acc[4][4];
    #pragma unroll
    for (int i = 0; i < 4; ++i) {
        rb[i] = rowbase(r0 + i);
        const float4 v = *reinterpret_cast<const float4*>(&sm.A[rb[i] + c0]);
        acc[i][0] = v.x; acc[i][1] = v.y; acc[i][2] = v.z; acc[i][3] = v.w;
    }
    #pragma unroll 8
    for (int p = 0; p < 32; ++p) {
        const float4 lr = *reinterpret_cast<const float4*>(&sm.LT[cur][p][r0]);
        const float4 lc = *reinterpret_cast<const float4*>(&sm.LT[cur][p][c0]);
        const float lrv[4] = {lr.x, lr.y, lr.z, lr.w};
        const float lcv[4] = {lc.x, lc.y, lc.z, lc.w};
        #pragma unroll
        for (int i = 0; i < 4; ++i)
            #pragma unroll
            for (int j = 0; j < 4; ++j)
                acc[i][j] -= lrv[i] * lcv[j];
    }
    if (tc4 < tr4) {
        #pragma unroll
        for (int i = 0; i < 4; ++i)
            *reinterpret_cast<float4*>(&sm.A[rb[i] + c0]) =
                make_float4(acc[i][0], acc[i][1], acc[i][2], acc[i][3]);
    } else {
        #pragma unroll
        for (int i = 0; i < 4; ++i)
            #pragma unroll
            for (int j = 0; j < 4; ++j)
                if (j <= i) sm.A[rb[i] + c0 + j] = acc[i][j];
    }
}

__device__ __forceinline__ void phaseC2(K2Smem& sm, int k, int cur, int a0)
{
    const int c0t = 4 * (k + 2);
    const int mrem = 32 - c0t;
    if (mrem <= 0) return;
    const int Tact = mrem * (mrem + 1) / 2;
    for (int a = a0; a < Tact; a += 320) {
        int t = (int)(0.5f * (__fsqrt_rn(8.f * a + 1.f) - 1.f));
        while ((t + 1) * (t + 2) / 2 <= a) ++t;
        while (t * (t + 1) / 2 > a) --t;
        const int tc = 31 - t;
        const int tr = 31 - (a - t * (t + 1) / 2);
        const int r0 = 8 * tr, cc0 = 8 * tc;

        float acc[8][8];
        int rbs[8];
        #pragma unroll
        for (int i = 0; i < 8; ++i) {
            rbs[i] = rowbase(r0 + i);
            const float4 v0 = *reinterpret_cast<const float4*>(&sm.A[rbs[i] + cc0]);
            const float4 v1 = *reinterpret_cast<const float4*>(&sm.A[rbs[i] + cc0 + 4]);
            acc[i][0] = v0.x; acc[i][1] = v0.y; acc[i][2] = v0.z; acc[i][3] = v0.w;
            acc[i][4] = v1.x; acc[i][5] = v1.y; acc[i][6] = v1.z; acc[i][7] = v1.w;
        }
        #pragma unroll 4
        for (int p = 0; p < 32; ++p) {
            const float4 lr0 = *reinterpret_cast<const float4*>(&sm.LT[cur][p][r0]);
            const float4 lr1 = *reinterpret_cast<const float4*>(&sm.LT[cur][p][r0 + 4]);
            const float4 lc0 = *reinterpret_cast<const float4*>(&sm.LT[cur][p][cc0]);
            const float4 lc1 = *reinterpret_cast<const float4*>(&sm.LT[cur][p][cc0 + 4]);
            const float lr[8] = {lr0.x, lr0.y, lr0.z, lr0.w, lr1.x, lr1.y, lr1.z, lr1.w};
            const float lc[8] = {lc0.x, lc0.y, lc0.z, lc0.w, lc1.x, lc1.y, lc1.z, lc1.w};
            #pragma unroll
            for (int i = 0; i < 8; ++i)
                #pragma unroll
                for (int j = 0; j < 8; ++j)
                    acc[i][j] -= lr[i] * lc[j];
        }
        if (tr != tc) {
            #pragma unroll
            for (int i = 0; i < 8; ++i) {
                *reinterpret_cast<float4*>(&sm.A[rbs[i] + cc0]) =
                    make_float4(acc[i][0], acc[i][1], acc[i][2], acc[i][3]);
                *reinterpret_cast<float4*>(&sm.A[rbs[i] + cc0 + 4]) =
                    make_float4(acc[i][4], acc[i][5], acc[i][6], acc[i][7]);
            }
        } else {
            #pragma unroll
            for (int i = 0; i < 8; ++i)
                #pragma unroll
                for (int j = 0; j < 8; ++j)
                    if (j <= i) sm.A[rbs[i] + cc0 + j] = acc[i][j];
        }
    }
}

__global__ void __launch_bounds__(K2T, 1)
chol_kernel(const float* __restrict__ targets, float* __restrict__ out)
{
    extern __shared__ char smraw[];
    K2Smem& sm = *reinterpret_cast<K2Smem*>(smraw);
    const int b = blockIdx.x, tid = threadIdx.x;

    {
        const float4* src = reinterpret_cast<const float4*>(g_gram[b]);
        float4* dst = reinterpret_cast<float4*>(sm.A);
        for (int i = tid; i < APACK_SIZE / 4; i += K2T) dst[i] = src[i];
    }
    if (tid < NPTS) sm.u[tid] = targets[(size_t)b * NPTS + tid];
    __syncthreads();

    if (tid < 32) phaseA(sm, 0, tid);
    __syncthreads();
    phaseB(sm, 0, 0, tid);
    __syncthreads();

    int cur = 0;
    #pragma unroll 1
    for (int k = 0; k < 7; ++k) {
        const int Pn = 32 * (k + 1);

        strip_update(sm, Pn, cur, tid);
        __syncthreads();

        if (tid < 192) {
            if (tid < 32) phaseA(sm, k + 1, tid);
            asm volatile("bar.sync 1, 192;" ::: "memory");
            phaseB(sm, k + 1, cur ^ 1, tid);
        } else {
            phaseC2(sm, k, cur, tid - 192);
        }
        __syncthreads();
        cur ^= 1;
    }

    for (int j = tid; j < NPTS; j += K2T)
        out[(size_t)b * NPTS + j] = targets[(size_t)b * NPTS + j] - sm.u[j];
}

extern "C" void kernel_launch(void* const* d_in, const int* in_sizes, int n_in,
                              void* d_out, int out_size)
{
    const float* data    = (const float*)d_in[0];   // [32, 256, 128] f32
    const float* targets = (const float*)d_in[1];   // [32, 256]      f32
    float* out = (float*)d_out;                     // [32, 256]      f32

    gram_kernel<<<BATCH * 36, 256>>>(data);

    const size_t smem_bytes = sizeof(K2Smem);
    cudaFuncSetAttribute(chol_kernel,
                         cudaFuncAttributeMaxDynamicSharedMemorySize,
                         (int)smem_bytes);
    chol_kernel<<<BATCH, K2T, smem_bytes>>>(targets, out);
}

// round 16
// speedup vs baseline: 1.7714x; 1.0500x over previous
#include <cuda_runtime.h>
#include <cstdint>
#include <cstddef>

// Ridge_51178830299316 — dual formulation, round 16.
// K1: 64x64 macro-tile Gram (10 tiles/batch, 4x4 register tiles per thread,
//     transposed-Xj smem) -> 3x lower LDS/FMA ratio than round 15's 2x2.
// K2: round-15 pipeline with Phase B restructured right-looking: finalize
//     Lr[p], then independent updates Lr[c>p] -= Lr[p]*DT[p][c]. Kills the
//     ~2000-cycle serial accumulation chain. Phase A stores DT (transposed
//     diag block) via conflict-free scalar STS.

#define NPTS   256
#define DIM    128
#define BATCH  32
#define K2T    512
#define APACK_SIZE 33280

__host__ __device__ __forceinline__ int rowbase(int r) {
    const int q = r >> 2, rem = r & 3;
    return 8 * q * (q - 1) + 4 * rem * q + 4 * r;
}

__device__ float g_gram[BATCH][APACK_SIZE];

// ============================ K1: Gram (64x64 macro-tiles) ================
struct K1Smem {
    float Xi[64][132];    // row-major rows of the ti panel
    float XjT[128][68];   // k-major (transposed) tj panel
};

__global__ void __launch_bounds__(256) gram_kernel(const float* __restrict__ data)
{
    extern __shared__ char k1raw[];
    K1Smem& sh = *reinterpret_cast<K1Smem*>(k1raw);

    const int bid = blockIdx.x;
    const int b = bid / 10, t10 = bid % 10;
    int ti = 0;
    while ((ti + 1) * (ti + 2) / 2 <= t10) ++ti;   // ti >= tj in 0..3
    const int tj = t10 - ti * (ti + 1) / 2;

    const float* Xb = data + (size_t)b * NPTS * DIM;
    const int tid = threadIdx.x;

    // Xi: coalesced LDG, conflict-free STS.
    for (int q = tid; q < 2048; q += 256) {
        const int r = q >> 5, c4 = q & 31;
        *reinterpret_cast<float4*>(&sh.Xi[r][c4 * 4]) =
            reinterpret_cast<const float4*>(Xb + (size_t)(ti * 64 + r) * DIM)[c4];
    }
    // XjT: lanes sweep j (consecutive STS); LDG strided but L2-resident.
    for (int q = tid; q < 2048; q += 256) {
        const int j = q & 63, c4 = q >> 6;
        const float4 v = reinterpret_cast<const float4*>(
            Xb + (size_t)(tj * 64 + j) * DIM)[c4];
        sh.XjT[4 * c4 + 0][j] = v.x;
        sh.XjT[4 * c4 + 1][j] = v.y;
        sh.XjT[4 * c4 + 2][j] = v.z;
        sh.XjT[4 * c4 + 3][j] = v.w;
    }
    __syncthreads();

    const int ty = tid >> 4, tx = tid & 15;
    const int r0l = 4 * ty, c0l = 4 * tx;
    float acc[4][4] = {};
    #pragma unroll 2
    for (int k4 = 0; k4 < 32; ++k4) {
        float4 xi[4], xj[4];
        #pragma unroll
        for (int i = 0; i < 4; ++i)
            xi[i] = *reinterpret_cast<const float4*>(&sh.Xi[r0l + i][k4 * 4]);
        #pragma unroll
        for (int e = 0; e < 4; ++e)
            xj[e] = *reinterpret_cast<const float4*>(&sh.XjT[k4 * 4 + e][c0l]);
        #pragma unroll
        for (int e = 0; e < 4; ++e) {
            const float xje[4] = {xj[e].x, xj[e].y, xj[e].z, xj[e].w};
            #pragma unroll
            for (int i = 0; i < 4; ++i) {
                const float xie = reinterpret_cast<const float*>(&xi[i])[e];
                #pragma unroll
                for (int j = 0; j < 4; ++j)
                    acc[i][j] = fmaf(xie, xje[j], acc[i][j]);
            }
        }
    }

    float* gg = g_gram[b];
    #pragma unroll
    for (int i = 0; i < 4; ++i) {
        const int r = ti * 64 + r0l + i;
        const int rb = rowbase(r);
        #pragma unroll
        for (int j = 0; j < 4; ++j) {
            const int c = tj * 64 + c0l + j;
            if (r >= c) gg[rb + c] = acc[i][j] + (r == c ? 1.f : 0.f);
        }
    }
}

// ==================== K2: pipelined Cholesky + forward sub ================
struct K2Smem {
    float A[APACK_SIZE];
    float u[NPTS];
    float z[32];
    float invD[32];
    float DT[32][32];          // DT[p][c] = L[c][p] (diag block, transposed)
    float LT[2][32][NPTS];
    float colbuf[2][32];
};

__device__ __forceinline__ void phaseA(K2Smem& sm, int kp, int tid)
{
    const int P = 32 * kp;
    const int rp = tid, gr = P + rp, rb = rowbase(gr);
    float arow[32];
    #pragma unroll
    for (int c = 0; c < 32; ++c) arow[c] = sm.A[rb + P + c];  // c>rp garbage, unused
    float ur = sm.u[gr];
    #pragma unroll
    for (int c = 0; c < 32; ++c) {
        const float d  = __shfl_sync(0xffffffffu, arow[c], c);
        const float uc = __shfl_sync(0xffffffffu, ur, c);
        const float rs = rsqrtf(d);
        const float zc = uc * rs;
        const float lrc = (rp > c) ? arow[c] * rs : 0.f;
        if (rp == c) { arow[c] = d * rs; sm.z[c] = zc; sm.invD[c] = rs; }
        if (rp > c)  { arow[c] = lrc; ur -= lrc * zc; }
        sm.colbuf[c & 1][rp] = lrc;
        __syncwarp();
        float cb[32];
        #pragma unroll
        for (int q = 0; q < 8; ++q)
            *reinterpret_cast<float4*>(&cb[4 * q]) =
                *reinterpret_cast<const float4*>(&sm.colbuf[c & 1][4 * q]);
        #pragma unroll
        for (int j = 0; j < 32; ++j)
            if (j > c) arow[j] -= lrc * cb[j];
    }
    sm.u[gr] = ur;
    // store row rp of L transposed: DT[p][rp] = L[rp][p]. p>rp lanes write
    // garbage that B never reads (guard c>p).
    #pragma unroll
    for (int p = 0; p < 32; ++p)
        sm.DT[p][rp] = arow[p];
}

__device__ __forceinline__ void phaseB(K2Smem& sm, int kp, int buf, int tid)
{
    const int P = 32 * kp;
    const int R = NPTS - P - 32;
    if (tid < R) {
        const int gr = P + 32 + tid, rb = rowbase(gr);
        float Lr[32];
        #pragma unroll
        for (int q = 0; q < 8; ++q)
            *reinterpret_cast<float4*>(&Lr[4 * q]) =
                *reinterpret_cast<const float4*>(&sm.A[rb + P + 4 * q]);
        #pragma unroll
        for (int p = 0; p < 32; ++p) {
            const float lp = Lr[p] * sm.invD[p];
            Lr[p] = lp;
            #pragma unroll
            for (int q = 0; q < 8; ++q) {
                if (4 * q + 3 > p) {   // compile-time: skip fully-dead quads
                    const float4 dt =
                        *reinterpret_cast<const float4*>(&sm.DT[p][4 * q]);
                    if (4 * q     > p) Lr[4 * q]     -= lp * dt.x;
                    if (4 * q + 1 > p) Lr[4 * q + 1] -= lp * dt.y;
                    if (4 * q + 2 > p) Lr[4 * q + 2] -= lp * dt.z;
                    Lr[4 * q + 3] -= lp * dt.w;
                }
            }
        }
        float du = 0.f;
        #pragma unroll
        for (int c = 0; c < 32; ++c) du += Lr[c] * sm.z[c];
        sm.u[gr] -= du;
        #pragma unroll
        for (int c = 0; c < 32; ++c) sm.LT[buf][c][gr] = Lr[c];
    }
}

__device__ __forceinline__ void strip_update(K2Smem& sm, int Pn, int cur, int tid)
{
    const int nrow4 = (NPTS - Pn) >> 2;
    const int tr4 = tid >> 3, tc4 = tid & 7;
    if (tr4 >= nrow4 || tc4 > tr4) return;
    const int r0 = Pn + 4 * tr4, c0 = Pn + 4 * tc4;

    int rb[4];
    float acc[4][4];
    #pragma unroll
    for (int i = 0; i < 4; ++i) {
        rb[i] = rowbase(r0 + i);
        const float4 v = *reinterpret_cast<const float4*>(&sm.A[rb[i] + c0]);
        acc[i][0] = v.x; acc[i][1] = v.y; acc[i][2] = v.z; acc[i][3] = v.w;
    }
    #pragma unroll 8
    for (int p = 0; p < 32; ++p) {
        const float4 lr = *reinterpret_cast<const float4*>(&sm.LT[cur][p][r0]);
        const float4 lc = *reinterpret_cast<const float4*>(&sm.LT[cur][p][c0]);
        const float lrv[4] = {lr.x, lr.y, lr.z, lr.w};
        const float lcv[4] = {lc.x, lc.y, lc.z, lc.w};
        #pragma unroll
        for (int i = 0; i < 4; ++i)
            #pragma unroll
            for (int j = 0; j < 4; ++j)
                acc[i][j] -= lrv[i] * lcv[j];
    }
    if (tc4 < tr4) {
        #pragma unroll
        for (int i = 0; i < 4; ++i)
            *reinterpret_cast<float4*>(&sm.A[rb[i] + c0]) =
                make_float4(acc[i][0], acc[i][1], acc[i][2], acc[i][3]);
    } else {
        #pragma unroll
        for (int i = 0; i < 4; ++i)
            #pragma unroll
            for (int j = 0; j < 4; ++j)
                if (j <= i) sm.A[rb[i] + c0 + j] = acc[i][j];
    }
}

__device__ __forceinline__ void phaseC2(K2Smem& sm, int k, int cur, int a0)
{
    const int c0t = 4 * (k + 2);
    const int mrem = 32 - c0t;
    if (mrem <= 0) return;
    const int Tact = mrem * (mrem + 1) / 2;
    for (int a = a0; a < Tact; a += 320) {
        int t = (int)(0.5f * (__fsqrt_rn(8.f * a + 1.f) - 1.f));
        while ((t + 1) * (t + 2) / 2 <= a) ++t;
        while (t * (t + 1) / 2 > a) --t;
        const int tc = 31 - t;
        const int tr = 31 - (a - t * (t + 1) / 2);
        const int r0 = 8 * tr, cc0 = 8 * tc;

        float acc[8][8];
        int rbs[8];
        #pragma unroll
        for (int i = 0; i < 8; ++i) {
            rbs[i] = rowbase(r0 + i);
            const float4 v0 = *reinterpret_cast<const float4*>(&sm.A[rbs[i] + cc0]);
            const float4 v1 = *reinterpret_cast<const float4*>(&sm.A[rbs[i] + cc0 + 4]);
            acc[i][0] = v0.x; acc[i][1] = v0.y; acc[i][2] = v0.z; acc[i][3] = v0.w;
            acc[i][4] = v1.x; acc[i][5] = v1.y; acc[i][6] = v1.z; acc[i][7] = v1.w;
        }
        #pragma unroll 4
        for (int p = 0; p < 32; ++p) {
            const float4 lr0 = *reinterpret_cast<const float4*>(&sm.LT[cur][p][r0]);
            const float4 lr1 = *reinterpret_cast<const float4*>(&sm.LT[cur][p][r0 + 4]);
            const float4 lc0 = *reinterpret_cast<const float4*>(&sm.LT[cur][p][cc0]);
            const float4 lc1 = *reinterpret_cast<const float4*>(&sm.LT[cur][p][cc0 + 4]);
            const float lr[8] = {lr0.x, lr0.y, lr0.z, lr0.w, lr1.x, lr1.y, lr1.z, lr1.w};
            const float lc[8] = {lc0.x, lc0.y, lc0.z, lc0.w, lc1.x, lc1.y, lc1.z, lc1.w};
            #pragma unroll
            for (int i = 0; i < 8; ++i)
                #pragma unroll
                for (int j = 0; j < 8; ++j)
                    acc[i][j] -= lr[i] * lc[j];
        }
        if (tr != tc) {
            #pragma unroll
            for (int i = 0; i < 8; ++i) {
                *reinterpret_cast<float4*>(&sm.A[rbs[i] + cc0]) =
                    make_float4(acc[i][0], acc[i][1], acc[i][2], acc[i][3]);
                *reinterpret_cast<float4*>(&sm.A[rbs[i] + cc0 + 4]) =
                    make_float4(acc[i][4], acc[i][5], acc[i][6], acc[i][7]);
            }
        } else {
            #pragma unroll
            for (int i = 0; i < 8; ++i)
                #pragma unroll
                for (int j = 0; j < 8; ++j)
                    if (j <= i) sm.A[rbs[i] + cc0 + j] = acc[i][j];
        }
    }
}

__global__ void __launch_bounds__(K2T, 1)
chol_kernel(const float* __restrict__ targets, float* __restrict__ out)
{
    extern __shared__ char smraw[];
    K2Smem& sm = *reinterpret_cast<K2Smem*>(smraw);
    const int b = blockIdx.x, tid = threadIdx.x;

    {
        const float4* src = reinterpret_cast<const float4*>(g_gram[b]);
        float4* dst = reinterpret_cast<float4*>(sm.A);
        for (int i = tid; i < APACK_SIZE / 4; i += K2T) dst[i] = src[i];
    }
    if (tid < NPTS) sm.u[tid] = targets[(size_t)b * NPTS + tid];
    __syncthreads();

    if (tid < 32) phaseA(sm, 0, tid);
    __syncthreads();
    phaseB(sm, 0, 0, tid);
    __syncthreads();

    int cur = 0;
    #pragma unroll 1
    for (int k = 0; k < 7; ++k) {
        const int Pn = 32 * (k + 1);

        strip_update(sm, Pn, cur, tid);
        __syncthreads();

        if (tid < 192) {
            if (tid < 32) phaseA(sm, k + 1, tid);
            asm volatile("bar.sync 1, 192;" ::: "memory");
            phaseB(sm, k + 1, cur ^ 1, tid);
        } else {
            phaseC2(sm, k, cur, tid - 192);
        }
        __syncthreads();
        cur ^= 1;
    }

    for (int j = tid; j < NPTS; j += K2T)
        out[(size_t)b * NPTS + j] = targets[(size_t)b * NPTS + j] - sm.u[j];
}

extern "C" void kernel_launch(void* const* d_in, const int* in_sizes, int n_in,
                              void* d_out, int out_size)
{
    const float* data    = (const float*)d_in[0];   // [32, 256, 128] f32
    const float* targets = (const float*)d_in[1];   // [32, 256]      f32
    float* out = (float*)d_out;                     // [32, 256]      f32

    const size_t k1_smem = sizeof(K1Smem);
    cudaFuncSetAttribute(gram_kernel,
                         cudaFuncAttributeMaxDynamicSharedMemorySize,
                         (int)k1_smem);
    gram_kernel<<<BATCH * 10, 256, k1_smem>>>(data);

    const size_t k2_smem = sizeof(K2Smem);
    cudaFuncSetAttribute(chol_kernel,
                         cudaFuncAttributeMaxDynamicSharedMemorySize,
                         (int)k2_smem);
    chol_kernel<<<BATCH, K2T, k2_smem>>>(targets, out);
}